// round 1
// baseline (speedup 1.0000x reference)
#include <cuda_runtime.h>
#include <cstdint>

#define M_TOTAL 32768
#define E_DIM 2048
#define L_DIM 64
#define H_DIM 128
#define S_LEN 4096

// Scratch (device globals: allocation-free rule)
__device__ float g_q[(size_t)M_TOTAL * H_DIM];
__device__ float g_k[(size_t)M_TOTAL * H_DIM];
__device__ float g_v[(size_t)M_TOTAL * H_DIM];

// ---------------- tf32 helpers ----------------

__device__ __forceinline__ void mma_tf32(float* d, const uint32_t* a, const uint32_t* b) {
    asm volatile(
        "mma.sync.aligned.m16n8k8.row.col.f32.tf32.tf32.f32 "
        "{%0,%1,%2,%3}, {%4,%5,%6,%7}, {%8,%9}, {%0,%1,%2,%3};\n"
        : "+f"(d[0]), "+f"(d[1]), "+f"(d[2]), "+f"(d[3])
        : "r"(a[0]), "r"(a[1]), "r"(a[2]), "r"(a[3]), "r"(b[0]), "r"(b[1]));
}

__device__ __forceinline__ uint32_t to_tf32(float x) {
    uint32_t h;
    asm("cvt.rna.tf32.f32 %0, %1;" : "=r"(h) : "f"(x));
    return h;
}

__device__ __forceinline__ void split_tf32(float x, uint32_t& hi, uint32_t& lo) {
    uint32_t h = to_tf32(x);
    hi = h;
    lo = __float_as_uint(x - __uint_as_float(h));  // |lo| ~ 2^-11 |x|; HW truncation of lo is negligible
}

// ---------------- 3xTF32 GEMM: C = A[M,K] @ concat(B1[K,N1], B2[K,N2]) ----------------
// C columns < N1 go to C1 (stride N1), the rest to C2 (stride N2).
// BM=128, KT=32, 256 threads = 8 warps as 4(m) x 2(n).

template <int BN>
__global__ void __launch_bounds__(256) gemm3x_kernel(
    const float* __restrict__ A,
    const float* __restrict__ B1, const float* __restrict__ B2,
    float* __restrict__ C1, float* __restrict__ C2,
    int K, int N1, int N2)
{
    constexpr int BM = 128;
    constexpr int KT = 32;
    constexpr int WNT = BN / 16;            // n8 tiles per warp
    constexpr int AS_STRIDE = KT + 4;       // 36: A-frag bank spread (lane/4)*4 + lane%4
    constexpr int BS_STRIDE = BN + 8;       // ≡ 8 mod 32: B-frag bank spread 8*(lane%4)+lane/4

    __shared__ float As[BM * AS_STRIDE];
    __shared__ float Bs[KT * BS_STRIDE];

    const int tid = threadIdx.x;
    const int warp = tid >> 5, lane = tid & 31;
    const int wm = warp >> 1;               // 0..3 -> 32 rows each
    const int wn = warp & 1;                // 0..1 -> BN/2 cols each
    const int lr = lane >> 2, lc = lane & 3;
    const int m0 = blockIdx.x * BM;
    const int n0 = blockIdx.y * BN;

    float acc[2][WNT][4];
#pragma unroll
    for (int mt = 0; mt < 2; mt++)
#pragma unroll
        for (int nt = 0; nt < WNT; nt++)
#pragma unroll
            for (int j = 0; j < 4; j++) acc[mt][nt][j] = 0.f;

    for (int kt = 0; kt < K; kt += KT) {
        // Load A tile: 128 x 32
#pragma unroll
        for (int r = 0; r < 4; r++) {
            int row = (tid >> 3) + r * 32;
            int c4 = (tid & 7) * 4;
            float4 vv = *(const float4*)(A + (size_t)(m0 + row) * K + kt + c4);
            *(float4*)&As[row * AS_STRIDE + c4] = vv;
        }
        // Load B tile: 32 x BN, column source selected by split point N1 (N1 % 64 == 0)
#pragma unroll
        for (int it = 0; it < (8 * BN) / 256; it++) {
            int i = it * 256 + tid;
            int row = i / (BN / 4);
            int c4 = (i % (BN / 4)) * 4;
            int gc = n0 + c4;
            const float* src = (gc < N1) ? (B1 + (size_t)(kt + row) * N1 + gc)
                                         : (B2 + (size_t)(kt + row) * N2 + (gc - N1));
            *(float4*)&Bs[row * BS_STRIDE + c4] = *(const float4*)src;
        }
        __syncthreads();

#pragma unroll
        for (int ks = 0; ks < 4; ks++) {
            uint32_t ah[2][4], al[2][4];
#pragma unroll
            for (int mt = 0; mt < 2; mt++) {
                int rb = wm * 32 + mt * 16;
                float f0 = As[(rb + lr) * AS_STRIDE + ks * 8 + lc];
                float f1 = As[(rb + lr + 8) * AS_STRIDE + ks * 8 + lc];
                float f2 = As[(rb + lr) * AS_STRIDE + ks * 8 + lc + 4];
                float f3 = As[(rb + lr + 8) * AS_STRIDE + ks * 8 + lc + 4];
                split_tf32(f0, ah[mt][0], al[mt][0]);
                split_tf32(f1, ah[mt][1], al[mt][1]);
                split_tf32(f2, ah[mt][2], al[mt][2]);
                split_tf32(f3, ah[mt][3], al[mt][3]);
            }
#pragma unroll
            for (int nt = 0; nt < WNT; nt++) {
                int c0 = wn * (BN / 2) + nt * 8 + lr;
                float g0 = Bs[(ks * 8 + lc) * BS_STRIDE + c0];
                float g1 = Bs[(ks * 8 + lc + 4) * BS_STRIDE + c0];
                uint32_t bh[2], bl[2];
                split_tf32(g0, bh[0], bl[0]);
                split_tf32(g1, bh[1], bl[1]);
#pragma unroll
                for (int mt = 0; mt < 2; mt++) {
                    mma_tf32(acc[mt][nt], ah[mt], bh);  // hi*hi
                    mma_tf32(acc[mt][nt], al[mt], bh);  // lo*hi
                    mma_tf32(acc[mt][nt], ah[mt], bl);  // hi*lo
                }
            }
        }
        __syncthreads();
    }

    // Store
#pragma unroll
    for (int mt = 0; mt < 2; mt++) {
        int r0 = m0 + wm * 32 + mt * 16 + lr;
#pragma unroll
        for (int nt = 0; nt < WNT; nt++) {
            int gc = n0 + wn * (BN / 2) + nt * 8 + lc * 2;
            float* dst;
            int stride, col;
            if (gc < N1) { dst = C1; stride = N1; col = gc; }
            else         { dst = C2; stride = N2; col = gc - N1; }
            float2 v01 = make_float2(acc[mt][nt][0], acc[mt][nt][1]);
            float2 v23 = make_float2(acc[mt][nt][2], acc[mt][nt][3]);
            *(float2*)(dst + (size_t)r0 * stride + col) = v01;
            *(float2*)(dst + (size_t)(r0 + 8) * stride + col) = v23;
        }
    }
}

// ---------------- Flash attention (causal) ----------------
// BLOCK_M=64 (4 warps x 16 rows), BLOCK_N=64, HEAD=128.
// QK^T: 3xTF32 (near-exact), PV: 1xTF32 with rna rounding.

constexpr int KS_STRIDE = 132;  // 128+4: frag addr (lane/4)*4 + lane%4 -> conflict-free
constexpr int VS_STRIDE = 136;  // 128+8: frag addr 8*(lane%4) + lane/4 -> conflict-free
constexpr int PS_STRIDE = 68;   // 64+4
constexpr int ATTN_SMEM_BYTES = (64 * KS_STRIDE + 64 * VS_STRIDE + 64 * PS_STRIDE) * 4;  // 86016

__global__ void __launch_bounds__(128, 2) attn_kernel(
    const float* __restrict__ q, const float* __restrict__ k,
    const float* __restrict__ v, float* __restrict__ out)
{
    extern __shared__ float sm[];
    float* Ks = sm;
    float* Vs = sm + 64 * KS_STRIDE;
    float* Ps = Vs + 64 * VS_STRIDE;

    const int idx = blockIdx.x;
    const int b = idx & 7;
    const int qb = 63 - (idx >> 3);         // longest (most kv blocks) first
    const int tid = threadIdx.x;
    const int warp = tid >> 5, lane = tid & 31;
    const int lr = lane >> 2, lc = lane & 3;

    const float* qB = q + (size_t)b * S_LEN * H_DIM;
    const float* kB = k + (size_t)b * S_LEN * H_DIM;
    const float* vB = v + (size_t)b * S_LEN * H_DIM;

    const int qrow0 = qb * 64 + warp * 16 + lr;  // within-batch q row (and +8)
    const float SCALE = 0.08838834764831845f;    // 1/sqrt(128), folded into q

    // q fragments in registers for all 16 k-steps
    float qreg[64];
#pragma unroll
    for (int ks = 0; ks < 16; ks++) {
        int c = ks * 8 + lc;
        qreg[ks * 4 + 0] = qB[(size_t)qrow0 * H_DIM + c] * SCALE;
        qreg[ks * 4 + 1] = qB[(size_t)(qrow0 + 8) * H_DIM + c] * SCALE;
        qreg[ks * 4 + 2] = qB[(size_t)qrow0 * H_DIM + c + 4] * SCALE;
        qreg[ks * 4 + 3] = qB[(size_t)(qrow0 + 8) * H_DIM + c + 4] * SCALE;
    }

    float acc[16][4];
#pragma unroll
    for (int nt = 0; nt < 16; nt++)
#pragma unroll
        for (int j = 0; j < 4; j++) acc[nt][j] = 0.f;
    float mrow[2] = {-INFINITY, -INFINITY};
    float lrow[2] = {0.f, 0.f};

    for (int kv = 0; kv <= qb; kv++) {
        __syncthreads();  // protect Ks/Vs (and Ps) from previous iteration's readers
        // Load K,V tile: 64 x 128 each. V pre-rounded to tf32 (rna).
#pragma unroll
        for (int rnd = 0; rnd < 16; rnd++) {
            int i = rnd * 128 + tid;
            int row = i >> 5;
            int c4 = (i & 31) * 4;
            float4 kk = *(const float4*)(kB + (size_t)(kv * 64 + row) * H_DIM + c4);
            *(float4*)&Ks[row * KS_STRIDE + c4] = kk;
            float4 vv = *(const float4*)(vB + (size_t)(kv * 64 + row) * H_DIM + c4);
            vv.x = __uint_as_float(to_tf32(vv.x));
            vv.y = __uint_as_float(to_tf32(vv.y));
            vv.z = __uint_as_float(to_tf32(vv.z));
            vv.w = __uint_as_float(to_tf32(vv.w));
            *(float4*)&Vs[row * VS_STRIDE + c4] = vv;
        }
        __syncthreads();

        // ---- S = q @ k^T (3xTF32) ----
        float sc[8][4];
#pragma unroll
        for (int nt = 0; nt < 8; nt++)
#pragma unroll
            for (int j = 0; j < 4; j++) sc[nt][j] = 0.f;

#pragma unroll
        for (int ks = 0; ks < 16; ks++) {
            uint32_t ah[4], al[4];
#pragma unroll
            for (int j = 0; j < 4; j++) split_tf32(qreg[ks * 4 + j], ah[j], al[j]);
#pragma unroll
            for (int nt = 0; nt < 8; nt++) {
                float g0 = Ks[(nt * 8 + lr) * KS_STRIDE + ks * 8 + lc];
                float g1 = Ks[(nt * 8 + lr) * KS_STRIDE + ks * 8 + lc + 4];
                uint32_t bh[2], bl[2];
                split_tf32(g0, bh[0], bl[0]);
                split_tf32(g1, bh[1], bl[1]);
                mma_tf32(sc[nt], ah, bh);
                mma_tf32(sc[nt], al, bh);
                mma_tf32(sc[nt], ah, bl);
            }
        }

        // Diagonal-block causal mask
        if (kv == qb) {
#pragma unroll
            for (int nt = 0; nt < 8; nt++)
#pragma unroll
                for (int j = 0; j < 4; j++) {
                    int col = nt * 8 + lc * 2 + (j & 1);
                    int row = warp * 16 + lr + (j >> 1) * 8;
                    if (col > row) sc[nt][j] = -INFINITY;
                }
        }

        // ---- online softmax ----
        float mnew[2] = {-INFINITY, -INFINITY};
#pragma unroll
        for (int nt = 0; nt < 8; nt++)
#pragma unroll
            for (int j = 0; j < 4; j++) mnew[j >> 1] = fmaxf(mnew[j >> 1], sc[nt][j]);
#pragma unroll
        for (int off = 1; off < 4; off <<= 1) {
            mnew[0] = fmaxf(mnew[0], __shfl_xor_sync(0xffffffffu, mnew[0], off));
            mnew[1] = fmaxf(mnew[1], __shfl_xor_sync(0xffffffffu, mnew[1], off));
        }
        float mtot0 = fmaxf(mrow[0], mnew[0]);
        float mtot1 = fmaxf(mrow[1], mnew[1]);
        float alpha0 = __expf(mrow[0] - mtot0);
        float alpha1 = __expf(mrow[1] - mtot1);
        mrow[0] = mtot0; mrow[1] = mtot1;

        float rs[2] = {0.f, 0.f};
#pragma unroll
        for (int nt = 0; nt < 8; nt++)
#pragma unroll
            for (int j = 0; j < 4; j++) {
                float p = __expf(sc[nt][j] - ((j >> 1) ? mtot1 : mtot0));
                sc[nt][j] = p;
                rs[j >> 1] += p;
            }
#pragma unroll
        for (int off = 1; off < 4; off <<= 1) {
            rs[0] += __shfl_xor_sync(0xffffffffu, rs[0], off);
            rs[1] += __shfl_xor_sync(0xffffffffu, rs[1], off);
        }
        lrow[0] = lrow[0] * alpha0 + rs[0];
        lrow[1] = lrow[1] * alpha1 + rs[1];

#pragma unroll
        for (int nt = 0; nt < 16; nt++) {
            acc[nt][0] *= alpha0; acc[nt][1] *= alpha0;
            acc[nt][2] *= alpha1; acc[nt][3] *= alpha1;
        }

        // P -> smem (per-warp private region), rna-rounded to tf32
        float* Pw = Ps + warp * 16 * PS_STRIDE;
#pragma unroll
        for (int nt = 0; nt < 8; nt++)
#pragma unroll
            for (int j = 0; j < 4; j++) {
                int row = lr + (j >> 1) * 8;
                int col = nt * 8 + lc * 2 + (j & 1);
                Pw[row * PS_STRIDE + col] = __uint_as_float(to_tf32(sc[nt][j]));
            }
        __syncwarp();

        // ---- O += P @ V (1xTF32) ----
#pragma unroll
        for (int ks2 = 0; ks2 < 8; ks2++) {
            uint32_t pa[4];
            pa[0] = __float_as_uint(Pw[lr * PS_STRIDE + ks2 * 8 + lc]);
            pa[1] = __float_as_uint(Pw[(lr + 8) * PS_STRIDE + ks2 * 8 + lc]);
            pa[2] = __float_as_uint(Pw[lr * PS_STRIDE + ks2 * 8 + lc + 4]);
            pa[3] = __float_as_uint(Pw[(lr + 8) * PS_STRIDE + ks2 * 8 + lc + 4]);
#pragma unroll
            for (int nt2 = 0; nt2 < 16; nt2++) {
                uint32_t vb[2];
                vb[0] = __float_as_uint(Vs[(ks2 * 8 + lc) * VS_STRIDE + nt2 * 8 + lr]);
                vb[1] = __float_as_uint(Vs[(ks2 * 8 + lc + 4) * VS_STRIDE + nt2 * 8 + lr]);
                mma_tf32(acc[nt2], pa, vb);
            }
        }
    }

    // Epilogue: normalize and store
    float inv0 = 1.f / lrow[0];
    float inv1 = 1.f / lrow[1];
    size_t obase = ((size_t)b * S_LEN + qrow0) * H_DIM;
#pragma unroll
    for (int nt2 = 0; nt2 < 16; nt2++) {
        int col = nt2 * 8 + lc * 2;
        *(float2*)(out + obase + col) =
            make_float2(acc[nt2][0] * inv0, acc[nt2][1] * inv0);
        *(float2*)(out + obase + (size_t)8 * H_DIM + col) =
            make_float2(acc[nt2][2] * inv1, acc[nt2][3] * inv1);
    }
}

// ---------------- launch ----------------

extern "C" void kernel_launch(void* const* d_in, const int* in_sizes, int n_in,
                              void* d_out, int out_size) {
    const float* x     = (const float*)d_in[0];
    const float* w_dkv = (const float*)d_in[1];
    const float* w_k   = (const float*)d_in[2];
    const float* w_v   = (const float*)d_in[3];
    const float* w_q   = (const float*)d_in[4];

    float* out = (float*)d_out;                          // [B,S,HEAD]
    float* latent = out + (size_t)M_TOTAL * H_DIM;       // [B,S,LATENT]

    float *qp, *kp, *vp;
    cudaGetSymbolAddress((void**)&qp, g_q);
    cudaGetSymbolAddress((void**)&kp, g_k);
    cudaGetSymbolAddress((void**)&vp, g_v);

    // 1) latent = x@w_dkv (-> d_out latent region), q = x@w_q (-> scratch). One pass over x.
    gemm3x_kernel<192><<<dim3(M_TOTAL / 128, 1), 256>>>(
        x, w_dkv, w_q, latent, qp, E_DIM, L_DIM, H_DIM);

    // 2) k = latent@w_k, v = latent@w_v
    gemm3x_kernel<64><<<dim3(M_TOTAL / 128, 4), 256>>>(
        latent, w_k, w_v, kp, vp, L_DIM, H_DIM, H_DIM);

    // 3) causal flash attention
    cudaFuncSetAttribute(attn_kernel, cudaFuncAttributeMaxDynamicSharedMemorySize,
                         ATTN_SMEM_BYTES);
    attn_kernel<<<512, 128, ATTN_SMEM_BYTES>>>(qp, kp, vp, out);
}

// round 2
// speedup vs baseline: 1.3759x; 1.3759x over previous
#include <cuda_runtime.h>
#include <cstdint>

#define M_TOTAL 32768
#define E_DIM 2048
#define L_DIM 64
#define H_DIM 128
#define S_LEN 4096

// Scratch (device globals: allocation-free rule)
__device__ float g_q[(size_t)M_TOTAL * H_DIM];
__device__ float g_k[(size_t)M_TOTAL * H_DIM];
__device__ float g_v[(size_t)M_TOTAL * H_DIM];

// ---------------- tf32 / async helpers ----------------

__device__ __forceinline__ void mma_tf32(float* d, const uint32_t* a, const uint32_t* b) {
    asm volatile(
        "mma.sync.aligned.m16n8k8.row.col.f32.tf32.tf32.f32 "
        "{%0,%1,%2,%3}, {%4,%5,%6,%7}, {%8,%9}, {%0,%1,%2,%3};\n"
        : "+f"(d[0]), "+f"(d[1]), "+f"(d[2]), "+f"(d[3])
        : "r"(a[0]), "r"(a[1]), "r"(a[2]), "r"(a[3]), "r"(b[0]), "r"(b[1]));
}

__device__ __forceinline__ uint32_t to_tf32(float x) {
    uint32_t h;
    asm("cvt.rna.tf32.f32 %0, %1;" : "=r"(h) : "f"(x));
    return h;
}

__device__ __forceinline__ void split_tf32(float x, uint32_t& hi, uint32_t& lo) {
    uint32_t h = to_tf32(x);
    hi = h;
    lo = __float_as_uint(x - __uint_as_float(h));
}

__device__ __forceinline__ void cp16(void* dst, const void* src) {
    uint32_t d = (uint32_t)__cvta_generic_to_shared(dst);
    asm volatile("cp.async.cg.shared.global [%0], [%1], 16;\n" :: "r"(d), "l"(src));
}
#define CP_COMMIT asm volatile("cp.async.commit_group;\n")
#define CP_WAIT0  asm volatile("cp.async.wait_group 0;\n")
#define CP_WAIT1  asm volatile("cp.async.wait_group 1;\n")

// ---------------- pipelined GEMM: C = A[M,K] @ concat(B1[K,N1], B2[K,N2]) ----------------
// Columns < exact_cols use 3xTF32 (near fp32-exact); others 2xTF32 (A exact, B rna).
// BM=128, KT=32, 256 threads = 8 warps as 4(m) x 2(n). cp.async double-buffered.

template <int BN>
__global__ void __launch_bounds__(256) gemm_kernel(
    const float* __restrict__ A,
    const float* __restrict__ B1, const float* __restrict__ B2,
    float* __restrict__ C1, float* __restrict__ C2,
    int K, int N1, int N2, int exact_cols)
{
    constexpr int BM = 128;
    constexpr int KT = 32;
    constexpr int WNT = BN / 16;
    constexpr int ASTR = KT + 4;            // 36
    constexpr int BSTR = BN + 8;
    constexpr int ASZ = BM * ASTR;
    constexpr int BSZ = KT * BSTR;
    constexpr int BUF = ASZ + BSZ;

    extern __shared__ float sh[];

    const int tid = threadIdx.x;
    const int warp = tid >> 5, lane = tid & 31;
    const int wm = warp >> 1;
    const int wn = warp & 1;
    const int lr = lane >> 2, lc = lane & 3;
    const int m0 = blockIdx.x * BM;
    const int n0 = blockIdx.y * BN;

    const int arow = tid >> 3;
    const int ac4 = (tid & 7) * 4;

    float acc[2][WNT][4];
#pragma unroll
    for (int mt = 0; mt < 2; mt++)
#pragma unroll
        for (int nt = 0; nt < WNT; nt++)
#pragma unroll
            for (int j = 0; j < 4; j++) acc[mt][nt][j] = 0.f;

    const int nk = K / KT;

    // prologue: stage tile 0
    {
        float* As = sh;
        float* Bs = sh + ASZ;
#pragma unroll
        for (int r = 0; r < 4; r++)
            cp16(&As[(arow + r * 32) * ASTR + ac4],
                 A + (size_t)(m0 + arow + r * 32) * K + ac4);
        constexpr int NB = (KT * BN / 4) / 256;
#pragma unroll
        for (int it = 0; it < NB; it++) {
            int i = it * 256 + tid;
            int brow = i / (BN / 4);
            int bc4 = (i % (BN / 4)) * 4;
            int gc = n0 + bc4;
            const float* src = (gc < N1) ? (B1 + (size_t)brow * N1 + gc)
                                         : (B2 + (size_t)brow * N2 + (gc - N1));
            cp16(&Bs[brow * BSTR + bc4], src);
        }
        CP_COMMIT;
    }

    for (int kt = 0; kt < nk; kt++) {
        // prefetch next tile into the other buffer
        if (kt + 1 < nk) {
            float* As = sh + ((kt + 1) & 1) * BUF;
            float* Bs = As + ASZ;
            int kb = (kt + 1) * KT;
#pragma unroll
            for (int r = 0; r < 4; r++)
                cp16(&As[(arow + r * 32) * ASTR + ac4],
                     A + (size_t)(m0 + arow + r * 32) * K + kb + ac4);
            constexpr int NB = (KT * BN / 4) / 256;
#pragma unroll
            for (int it = 0; it < NB; it++) {
                int i = it * 256 + tid;
                int brow = i / (BN / 4);
                int bc4 = (i % (BN / 4)) * 4;
                int gc = n0 + bc4;
                const float* src = (gc < N1) ? (B1 + (size_t)(kb + brow) * N1 + gc)
                                             : (B2 + (size_t)(kb + brow) * N2 + (gc - N1));
                cp16(&Bs[brow * BSTR + bc4], src);
            }
            CP_COMMIT;
            CP_WAIT1;
        } else {
            CP_WAIT0;
        }
        __syncthreads();

        const float* As = sh + (kt & 1) * BUF;
        const float* Bs = As + ASZ;

#pragma unroll
        for (int ks = 0; ks < 4; ks++) {
            uint32_t ah[2][4], al[2][4];
#pragma unroll
            for (int mt = 0; mt < 2; mt++) {
                int rb = wm * 32 + mt * 16;
                split_tf32(As[(rb + lr) * ASTR + ks * 8 + lc],     ah[mt][0], al[mt][0]);
                split_tf32(As[(rb + lr + 8) * ASTR + ks * 8 + lc], ah[mt][1], al[mt][1]);
                split_tf32(As[(rb + lr) * ASTR + ks * 8 + lc + 4],     ah[mt][2], al[mt][2]);
                split_tf32(As[(rb + lr + 8) * ASTR + ks * 8 + lc + 4], ah[mt][3], al[mt][3]);
            }
#pragma unroll
            for (int nt = 0; nt < WNT; nt++) {
                int c0 = wn * (BN / 2) + nt * 8 + lr;
                float g0 = Bs[(ks * 8 + lc) * BSTR + c0];
                float g1 = Bs[(ks * 8 + lc + 4) * BSTR + c0];
                bool ex = (n0 + wn * (BN / 2) + nt * 8) < exact_cols;
                if (ex) {
                    uint32_t bh[2], bl[2];
                    split_tf32(g0, bh[0], bl[0]);
                    split_tf32(g1, bh[1], bl[1]);
#pragma unroll
                    for (int mt = 0; mt < 2; mt++) {
                        mma_tf32(acc[mt][nt], ah[mt], bh);
                        mma_tf32(acc[mt][nt], al[mt], bh);
                        mma_tf32(acc[mt][nt], ah[mt], bl);
                    }
                } else {
                    uint32_t bh[2];
                    bh[0] = to_tf32(g0);
                    bh[1] = to_tf32(g1);
#pragma unroll
                    for (int mt = 0; mt < 2; mt++) {
                        mma_tf32(acc[mt][nt], ah[mt], bh);
                        mma_tf32(acc[mt][nt], al[mt], bh);
                    }
                }
            }
        }
        __syncthreads();
    }

    // Store
#pragma unroll
    for (int mt = 0; mt < 2; mt++) {
        int r0 = m0 + wm * 32 + mt * 16 + lr;
#pragma unroll
        for (int nt = 0; nt < WNT; nt++) {
            int gc = n0 + wn * (BN / 2) + nt * 8 + lc * 2;
            float* dst;
            int stride, col;
            if (gc < N1) { dst = C1; stride = N1; col = gc; }
            else         { dst = C2; stride = N2; col = gc - N1; }
            *(float2*)(dst + (size_t)r0 * stride + col) =
                make_float2(acc[mt][nt][0], acc[mt][nt][1]);
            *(float2*)(dst + (size_t)(r0 + 8) * stride + col) =
                make_float2(acc[mt][nt][2], acc[mt][nt][3]);
        }
    }
}

// ---------------- Flash attention (causal) ----------------
// BLOCK_M=64 (4 warps x 16 rows), BLOCK_N=64, HEAD=128.
// QK^T: 2xTF32 (q split hi/lo exact, K rna-rounded in smem), PV: 1xTF32 rna.

constexpr int KS_STRIDE = 132;
constexpr int VS_STRIDE = 136;
constexpr int PS_STRIDE = 68;
constexpr int ATTN_SMEM_BYTES = (64 * KS_STRIDE + 64 * VS_STRIDE + 64 * PS_STRIDE) * 4;  // 86016

__global__ void __launch_bounds__(128, 2) attn_kernel(
    const float* __restrict__ q, const float* __restrict__ k,
    const float* __restrict__ v, float* __restrict__ out)
{
    extern __shared__ float sm[];
    float* Ks = sm;
    float* Vs = sm + 64 * KS_STRIDE;
    float* Ps = Vs + 64 * VS_STRIDE;

    const int idx = blockIdx.x;
    const int b = idx & 7;
    const int qb = 63 - (idx >> 3);         // longest first
    const int tid = threadIdx.x;
    const int warp = tid >> 5, lane = tid & 31;
    const int lr = lane >> 2, lc = lane & 3;

    const float* qB = q + (size_t)b * S_LEN * H_DIM;
    const float* kB = k + (size_t)b * S_LEN * H_DIM;
    const float* vB = v + (size_t)b * S_LEN * H_DIM;

    const int qrow0 = qb * 64 + warp * 16 + lr;
    const float SCALE = 0.08838834764831845f;  // 1/sqrt(128)

    // q fragments in registers for all 16 k-steps
    float qreg[64];
#pragma unroll
    for (int ks = 0; ks < 16; ks++) {
        int c = ks * 8 + lc;
        qreg[ks * 4 + 0] = qB[(size_t)qrow0 * H_DIM + c] * SCALE;
        qreg[ks * 4 + 1] = qB[(size_t)(qrow0 + 8) * H_DIM + c] * SCALE;
        qreg[ks * 4 + 2] = qB[(size_t)qrow0 * H_DIM + c + 4] * SCALE;
        qreg[ks * 4 + 3] = qB[(size_t)(qrow0 + 8) * H_DIM + c + 4] * SCALE;
    }

    float acc[16][4];
#pragma unroll
    for (int nt = 0; nt < 16; nt++)
#pragma unroll
        for (int j = 0; j < 4; j++) acc[nt][j] = 0.f;
    float mrow[2] = {-INFINITY, -INFINITY};
    float lrow[2] = {0.f, 0.f};

    const int row64 = tid >> 5;       // cp.async row base within 64 (i>>5 pattern)
    const int c4 = (tid & 31) * 4;

    for (int kv = 0; kv <= qb; kv++) {
        __syncthreads();  // previous tile's readers done before overwrite

        // cp.async K,V tiles (64x128 each)
#pragma unroll
        for (int rnd = 0; rnd < 16; rnd++) {
            int row = row64 + rnd * 4;
            cp16(&Ks[row * KS_STRIDE + c4], kB + (size_t)(kv * 64 + row) * H_DIM + c4);
            cp16(&Vs[row * VS_STRIDE + c4], vB + (size_t)(kv * 64 + row) * H_DIM + c4);
        }
        CP_COMMIT;
        CP_WAIT0;
        __syncthreads();

        // in-place rna rounding of K and V to tf32
#pragma unroll
        for (int rnd = 0; rnd < 16; rnd++) {
            int row = row64 + rnd * 4;
            float4* pk = (float4*)&Ks[row * KS_STRIDE + c4];
            float4 kk = *pk;
            kk.x = __uint_as_float(to_tf32(kk.x));
            kk.y = __uint_as_float(to_tf32(kk.y));
            kk.z = __uint_as_float(to_tf32(kk.z));
            kk.w = __uint_as_float(to_tf32(kk.w));
            *pk = kk;
            float4* pv = (float4*)&Vs[row * VS_STRIDE + c4];
            float4 vv = *pv;
            vv.x = __uint_as_float(to_tf32(vv.x));
            vv.y = __uint_as_float(to_tf32(vv.y));
            vv.z = __uint_as_float(to_tf32(vv.z));
            vv.w = __uint_as_float(to_tf32(vv.w));
            *pv = vv;
        }
        __syncthreads();

        // ---- S = q @ k^T (2xTF32: q split, K pre-rounded) ----
        float sc[8][4];
#pragma unroll
        for (int nt = 0; nt < 8; nt++)
#pragma unroll
            for (int j = 0; j < 4; j++) sc[nt][j] = 0.f;

#pragma unroll
        for (int ks = 0; ks < 16; ks++) {
            uint32_t ah[4], al[4];
#pragma unroll
            for (int j = 0; j < 4; j++) split_tf32(qreg[ks * 4 + j], ah[j], al[j]);
#pragma unroll
            for (int nt = 0; nt < 8; nt++) {
                uint32_t bh[2];
                bh[0] = __float_as_uint(Ks[(nt * 8 + lr) * KS_STRIDE + ks * 8 + lc]);
                bh[1] = __float_as_uint(Ks[(nt * 8 + lr) * KS_STRIDE + ks * 8 + lc + 4]);
                mma_tf32(sc[nt], ah, bh);
                mma_tf32(sc[nt], al, bh);
            }
        }

        // Diagonal-block causal mask
        if (kv == qb) {
#pragma unroll
            for (int nt = 0; nt < 8; nt++)
#pragma unroll
                for (int j = 0; j < 4; j++) {
                    int col = nt * 8 + lc * 2 + (j & 1);
                    int row = warp * 16 + lr + (j >> 1) * 8;
                    if (col > row) sc[nt][j] = -INFINITY;
                }
        }

        // ---- online softmax ----
        float mnew[2] = {-INFINITY, -INFINITY};
#pragma unroll
        for (int nt = 0; nt < 8; nt++)
#pragma unroll
            for (int j = 0; j < 4; j++) mnew[j >> 1] = fmaxf(mnew[j >> 1], sc[nt][j]);
#pragma unroll
        for (int off = 1; off < 4; off <<= 1) {
            mnew[0] = fmaxf(mnew[0], __shfl_xor_sync(0xffffffffu, mnew[0], off));
            mnew[1] = fmaxf(mnew[1], __shfl_xor_sync(0xffffffffu, mnew[1], off));
        }
        float mtot0 = fmaxf(mrow[0], mnew[0]);
        float mtot1 = fmaxf(mrow[1], mnew[1]);
        float alpha0 = __expf(mrow[0] - mtot0);
        float alpha1 = __expf(mrow[1] - mtot1);
        mrow[0] = mtot0; mrow[1] = mtot1;

        float rs[2] = {0.f, 0.f};
#pragma unroll
        for (int nt = 0; nt < 8; nt++)
#pragma unroll
            for (int j = 0; j < 4; j++) {
                float p = __expf(sc[nt][j] - ((j >> 1) ? mtot1 : mtot0));
                sc[nt][j] = p;
                rs[j >> 1] += p;
            }
#pragma unroll
        for (int off = 1; off < 4; off <<= 1) {
            rs[0] += __shfl_xor_sync(0xffffffffu, rs[0], off);
            rs[1] += __shfl_xor_sync(0xffffffffu, rs[1], off);
        }
        lrow[0] = lrow[0] * alpha0 + rs[0];
        lrow[1] = lrow[1] * alpha1 + rs[1];

#pragma unroll
        for (int nt = 0; nt < 16; nt++) {
            acc[nt][0] *= alpha0; acc[nt][1] *= alpha0;
            acc[nt][2] *= alpha1; acc[nt][3] *= alpha1;
        }

        // P -> smem (per-warp private), rna-rounded
        float* Pw = Ps + warp * 16 * PS_STRIDE;
#pragma unroll
        for (int nt = 0; nt < 8; nt++)
#pragma unroll
            for (int j = 0; j < 4; j++) {
                int row = lr + (j >> 1) * 8;
                int col = nt * 8 + lc * 2 + (j & 1);
                Pw[row * PS_STRIDE + col] = __uint_as_float(to_tf32(sc[nt][j]));
            }
        __syncwarp();

        // ---- O += P @ V (1xTF32, V pre-rounded) ----
#pragma unroll
        for (int ks2 = 0; ks2 < 8; ks2++) {
            uint32_t pa[4];
            pa[0] = __float_as_uint(Pw[lr * PS_STRIDE + ks2 * 8 + lc]);
            pa[1] = __float_as_uint(Pw[(lr + 8) * PS_STRIDE + ks2 * 8 + lc]);
            pa[2] = __float_as_uint(Pw[lr * PS_STRIDE + ks2 * 8 + lc + 4]);
            pa[3] = __float_as_uint(Pw[(lr + 8) * PS_STRIDE + ks2 * 8 + lc + 4]);
#pragma unroll
            for (int nt2 = 0; nt2 < 16; nt2++) {
                uint32_t vb[2];
                vb[0] = __float_as_uint(Vs[(ks2 * 8 + lc) * VS_STRIDE + nt2 * 8 + lr]);
                vb[1] = __float_as_uint(Vs[(ks2 * 8 + lc + 4) * VS_STRIDE + nt2 * 8 + lr]);
                mma_tf32(acc[nt2], pa, vb);
            }
        }
    }

    // Epilogue
    float inv0 = 1.f / lrow[0];
    float inv1 = 1.f / lrow[1];
    size_t obase = ((size_t)b * S_LEN + qrow0) * H_DIM;
#pragma unroll
    for (int nt2 = 0; nt2 < 16; nt2++) {
        int col = nt2 * 8 + lc * 2;
        *(float2*)(out + obase + col) =
            make_float2(acc[nt2][0] * inv0, acc[nt2][1] * inv0);
        *(float2*)(out + obase + (size_t)8 * H_DIM + col) =
            make_float2(acc[nt2][2] * inv1, acc[nt2][3] * inv1);
    }
}

// ---------------- launch ----------------

extern "C" void kernel_launch(void* const* d_in, const int* in_sizes, int n_in,
                              void* d_out, int out_size) {
    const float* x     = (const float*)d_in[0];
    const float* w_dkv = (const float*)d_in[1];
    const float* w_k   = (const float*)d_in[2];
    const float* w_v   = (const float*)d_in[3];
    const float* w_q   = (const float*)d_in[4];

    float* out = (float*)d_out;                          // [B,S,HEAD]
    float* latent = out + (size_t)M_TOTAL * H_DIM;       // [B,S,LATENT]

    float *qp, *kp, *vp;
    cudaGetSymbolAddress((void**)&qp, g_q);
    cudaGetSymbolAddress((void**)&kp, g_k);
    cudaGetSymbolAddress((void**)&vp, g_v);

    constexpr int SMEM1 = 2 * (128 * 36 + 32 * (192 + 8)) * 4;  // 88064
    constexpr int SMEM2 = 2 * (128 * 36 + 32 * (64 + 8)) * 4;   // 55296

    static bool attrs_set = false;
    if (!attrs_set) {
        cudaFuncSetAttribute(gemm_kernel<192>,
                             cudaFuncAttributeMaxDynamicSharedMemorySize, SMEM1);
        cudaFuncSetAttribute(gemm_kernel<64>,
                             cudaFuncAttributeMaxDynamicSharedMemorySize, SMEM2);
        cudaFuncSetAttribute(attn_kernel,
                             cudaFuncAttributeMaxDynamicSharedMemorySize, ATTN_SMEM_BYTES);
        attrs_set = true;
    }

    // 1) latent = x@w_dkv (3x, cols<64) -> d_out latent; q = x@w_q (2x) -> scratch.
    gemm_kernel<192><<<dim3(M_TOTAL / 128, 1), 256, SMEM1>>>(
        x, w_dkv, w_q, latent, qp, E_DIM, L_DIM, H_DIM, 64);

    // 2) k = latent@w_k, v = latent@w_v (3x everywhere; K=64, cheap)
    gemm_kernel<64><<<dim3(M_TOTAL / 128, 4), 256, SMEM2>>>(
        latent, w_k, w_v, kp, vp, L_DIM, H_DIM, H_DIM, 1 << 30);

    // 3) causal flash attention
    attn_kernel<<<512, 128, ATTN_SMEM_BYTES>>>(qp, kp, vp, out);
}

// round 4
// speedup vs baseline: 1.4471x; 1.0518x over previous
#include <cuda_runtime.h>
#include <cstdint>

#define M_TOTAL 32768
#define E_DIM 2048
#define L_DIM 64
#define H_DIM 128
#define S_LEN 4096

// Scratch (device globals: allocation-free rule)
__device__ float g_q[(size_t)M_TOTAL * H_DIM];
__device__ float g_k[(size_t)M_TOTAL * H_DIM];
__device__ float g_v[(size_t)M_TOTAL * H_DIM];

// ---------------- tf32 / async helpers ----------------

__device__ __forceinline__ void mma_tf32(float* d, const uint32_t* a, const uint32_t* b) {
    asm volatile(
        "mma.sync.aligned.m16n8k8.row.col.f32.tf32.tf32.f32 "
        "{%0,%1,%2,%3}, {%4,%5,%6,%7}, {%8,%9}, {%0,%1,%2,%3};\n"
        : "+f"(d[0]), "+f"(d[1]), "+f"(d[2]), "+f"(d[3])
        : "r"(a[0]), "r"(a[1]), "r"(a[2]), "r"(a[3]), "r"(b[0]), "r"(b[1]));
}

__device__ __forceinline__ uint32_t to_tf32(float x) {
    uint32_t h;
    asm("cvt.rna.tf32.f32 %0, %1;" : "=r"(h) : "f"(x));
    return h;
}

__device__ __forceinline__ void split_tf32(float x, uint32_t& hi, uint32_t& lo) {
    uint32_t h = to_tf32(x);
    hi = h;
    lo = __float_as_uint(x - __uint_as_float(h));
}

__device__ __forceinline__ void cp16(void* dst, const void* src) {
    uint32_t d = (uint32_t)__cvta_generic_to_shared(dst);
    asm volatile("cp.async.cg.shared.global [%0], [%1], 16;\n" :: "r"(d), "l"(src));
}
#define CP_COMMIT asm volatile("cp.async.commit_group;\n")
#define CP_WAIT0  asm volatile("cp.async.wait_group 0;\n")
#define CP_WAIT1  asm volatile("cp.async.wait_group 1;\n")

// ---------------- pipelined GEMM: C = A[M,K] @ concat(B1[K,N1], B2[K,N2]) ----------------
// Columns < exact_cols use 3xTF32 (near fp32-exact); others 2xTF32 (A exact, B rna).
// BM=128, KT=32, 512 threads = 16 warps as 4(m) x 4(n). cp.async double-buffered.

template <int BN>
__global__ void __launch_bounds__(512) gemm_kernel(
    const float* __restrict__ A,
    const float* __restrict__ B1, const float* __restrict__ B2,
    float* __restrict__ C1, float* __restrict__ C2,
    int K, int N1, int N2, int exact_cols)
{
    constexpr int BM = 128;
    constexpr int KTL = 32;
    constexpr int WNT = BN / 32;            // n8 tiles per warp (4 n-warps)
    constexpr int ASTR = KTL + 4;           // 36
    constexpr int BSTR = BN + 8;
    constexpr int ASZ = BM * ASTR;
    constexpr int BSZ = KTL * BSTR;
    constexpr int BUF = ASZ + BSZ;

    extern __shared__ float sh[];

    const int tid = threadIdx.x;
    const int warp = tid >> 5, lane = tid & 31;
    const int wm = warp >> 2;               // 0..3 -> 32 rows each
    const int wn = warp & 3;                // 0..3 -> BN/4 cols each
    const int lr = lane >> 2, lc = lane & 3;
    const int m0 = blockIdx.x * BM;
    const int n0 = blockIdx.y * BN;

    const int arow = tid >> 2;              // 0..127
    const int ac4 = (tid & 3) * 4;          // 0,4,8,12 (and +16)

    float acc[2][WNT][4];
#pragma unroll
    for (int mt = 0; mt < 2; mt++)
#pragma unroll
        for (int nt = 0; nt < WNT; nt++)
#pragma unroll
            for (int j = 0; j < 4; j++) acc[mt][nt][j] = 0.f;

    const int nk = K / KTL;

    // prologue: stage tile 0
    {
        float* As = sh;
        float* Bs = sh + ASZ;
        cp16(&As[arow * ASTR + ac4],      A + (size_t)(m0 + arow) * K + ac4);
        cp16(&As[arow * ASTR + ac4 + 16], A + (size_t)(m0 + arow) * K + ac4 + 16);
        constexpr int NB = (KTL * BN / 4) / 512;
#pragma unroll
        for (int it = 0; it < NB; it++) {
            int i = it * 512 + tid;
            int brow = i / (BN / 4);
            int bc4 = (i % (BN / 4)) * 4;
            int gc = n0 + bc4;
            const float* src = (gc < N1) ? (B1 + (size_t)brow * N1 + gc)
                                         : (B2 + (size_t)brow * N2 + (gc - N1));
            cp16(&Bs[brow * BSTR + bc4], src);
        }
        CP_COMMIT;
    }

    for (int kt = 0; kt < nk; kt++) {
        // prefetch next tile into the other buffer
        if (kt + 1 < nk) {
            float* As = sh + ((kt + 1) & 1) * BUF;
            float* Bs = As + ASZ;
            int kb = (kt + 1) * KTL;
            cp16(&As[arow * ASTR + ac4],      A + (size_t)(m0 + arow) * K + kb + ac4);
            cp16(&As[arow * ASTR + ac4 + 16], A + (size_t)(m0 + arow) * K + kb + ac4 + 16);
            constexpr int NB = (KTL * BN / 4) / 512;
#pragma unroll
            for (int it = 0; it < NB; it++) {
                int i = it * 512 + tid;
                int brow = i / (BN / 4);
                int bc4 = (i % (BN / 4)) * 4;
                int gc = n0 + bc4;
                const float* src = (gc < N1) ? (B1 + (size_t)(kb + brow) * N1 + gc)
                                             : (B2 + (size_t)(kb + brow) * N2 + (gc - N1));
                cp16(&Bs[brow * BSTR + bc4], src);
            }
            CP_COMMIT;
            CP_WAIT1;
        } else {
            CP_WAIT0;
        }
        __syncthreads();

        const float* As = sh + (kt & 1) * BUF;
        const float* Bs = As + ASZ;

#pragma unroll
        for (int ks = 0; ks < 4; ks++) {
            uint32_t ah[2][4], al[2][4];
#pragma unroll
            for (int mt = 0; mt < 2; mt++) {
                int rb = wm * 32 + mt * 16;
                split_tf32(As[(rb + lr) * ASTR + ks * 8 + lc],     ah[mt][0], al[mt][0]);
                split_tf32(As[(rb + lr + 8) * ASTR + ks * 8 + lc], ah[mt][1], al[mt][1]);
                split_tf32(As[(rb + lr) * ASTR + ks * 8 + lc + 4],     ah[mt][2], al[mt][2]);
                split_tf32(As[(rb + lr + 8) * ASTR + ks * 8 + lc + 4], ah[mt][3], al[mt][3]);
            }
#pragma unroll
            for (int nt = 0; nt < WNT; nt++) {
                int c0 = wn * (BN / 4) + nt * 8 + lr;
                float g0 = Bs[(ks * 8 + lc) * BSTR + c0];
                float g1 = Bs[(ks * 8 + lc + 4) * BSTR + c0];
                bool ex = (n0 + wn * (BN / 4) + nt * 8) < exact_cols;
                if (ex) {
                    uint32_t bh[2], bl[2];
                    split_tf32(g0, bh[0], bl[0]);
                    split_tf32(g1, bh[1], bl[1]);
#pragma unroll
                    for (int mt = 0; mt < 2; mt++) {
                        mma_tf32(acc[mt][nt], ah[mt], bh);
                        mma_tf32(acc[mt][nt], al[mt], bh);
                        mma_tf32(acc[mt][nt], ah[mt], bl);
                    }
                } else {
                    uint32_t bh[2];
                    bh[0] = to_tf32(g0);
                    bh[1] = to_tf32(g1);
#pragma unroll
                    for (int mt = 0; mt < 2; mt++) {
                        mma_tf32(acc[mt][nt], ah[mt], bh);
                        mma_tf32(acc[mt][nt], al[mt], bh);
                    }
                }
            }
        }
        __syncthreads();
    }

    // Store
#pragma unroll
    for (int mt = 0; mt < 2; mt++) {
        int r0 = m0 + wm * 32 + mt * 16 + lr;
#pragma unroll
        for (int nt = 0; nt < WNT; nt++) {
            int gc = n0 + wn * (BN / 4) + nt * 8 + lc * 2;
            float* dst;
            int stride, col;
            if (gc < N1) { dst = C1; stride = N1; col = gc; }
            else         { dst = C2; stride = N2; col = gc - N1; }
            *(float2*)(dst + (size_t)r0 * stride + col) =
                make_float2(acc[mt][nt][0], acc[mt][nt][1]);
            *(float2*)(dst + (size_t)(r0 + 8) * stride + col) =
                make_float2(acc[mt][nt][2], acc[mt][nt][3]);
        }
    }
}

// ---------------- Flash attention (causal) ----------------
// BLOCK_M=64 (4 warps x 16 rows), BLOCK_N=64, HEAD=128.
// QK^T: 2xTF32 (q pre-split hi/lo in regs, K truncated by HW), PV: 1xTF32
// (P rna-rounded, V truncated by HW).

constexpr int KS_STRIDE = 132;
constexpr int VS_STRIDE = 136;
constexpr int PS_STRIDE = 68;
constexpr int ATTN_SMEM_BYTES = (64 * KS_STRIDE + 64 * VS_STRIDE + 64 * PS_STRIDE) * 4;

__global__ void __launch_bounds__(128, 2) attn_kernel(
    const float* __restrict__ q, const float* __restrict__ k,
    const float* __restrict__ v, float* __restrict__ out)
{
    extern __shared__ float sm[];
    float* Ks = sm;
    float* Vs = sm + 64 * KS_STRIDE;
    float* Ps = Vs + 64 * VS_STRIDE;

    const int idx = blockIdx.x;
    const int b = idx & 7;
    const int qb = 63 - (idx >> 3);         // longest first
    const int tid = threadIdx.x;
    const int warp = tid >> 5, lane = tid & 31;
    const int lr = lane >> 2, lc = lane & 3;

    const float* qB = q + (size_t)b * S_LEN * H_DIM;
    const float* kB = k + (size_t)b * S_LEN * H_DIM;
    const float* vB = v + (size_t)b * S_LEN * H_DIM;

    const int qrow0 = qb * 64 + warp * 16 + lr;
    const float SCALE = 0.08838834764831845f;  // 1/sqrt(128)

    // q fragments pre-split hi/lo, kept in registers for all 16 k-steps
    uint32_t qh[64], ql[64];
#pragma unroll
    for (int ks = 0; ks < 16; ks++) {
        int c = ks * 8 + lc;
        split_tf32(qB[(size_t)qrow0 * H_DIM + c] * SCALE,       qh[ks * 4 + 0], ql[ks * 4 + 0]);
        split_tf32(qB[(size_t)(qrow0 + 8) * H_DIM + c] * SCALE, qh[ks * 4 + 1], ql[ks * 4 + 1]);
        split_tf32(qB[(size_t)qrow0 * H_DIM + c + 4] * SCALE,       qh[ks * 4 + 2], ql[ks * 4 + 2]);
        split_tf32(qB[(size_t)(qrow0 + 8) * H_DIM + c + 4] * SCALE, qh[ks * 4 + 3], ql[ks * 4 + 3]);
    }

    float acc[16][4];
#pragma unroll
    for (int nt = 0; nt < 16; nt++)
#pragma unroll
        for (int j = 0; j < 4; j++) acc[nt][j] = 0.f;
    float mrow[2] = {-INFINITY, -INFINITY};
    float lrow[2] = {0.f, 0.f};

    const int row64 = tid >> 5;
    const int c4 = (tid & 31) * 4;

    for (int kv = 0; kv <= qb; kv++) {
        __syncthreads();  // previous tile's readers done before overwrite

        // cp.async K,V tiles (64x128 each); no rounding pass — HW truncates fp32->tf32
#pragma unroll
        for (int rnd = 0; rnd < 16; rnd++) {
            int row = row64 + rnd * 4;
            cp16(&Ks[row * KS_STRIDE + c4], kB + (size_t)(kv * 64 + row) * H_DIM + c4);
            cp16(&Vs[row * VS_STRIDE + c4], vB + (size_t)(kv * 64 + row) * H_DIM + c4);
        }
        CP_COMMIT;
        CP_WAIT0;
        __syncthreads();

        // ---- S = q @ k^T (2xTF32: q split, K truncated) ----
        float sc[8][4];
#pragma unroll
        for (int nt = 0; nt < 8; nt++)
#pragma unroll
            for (int j = 0; j < 4; j++) sc[nt][j] = 0.f;

#pragma unroll
        for (int ks = 0; ks < 16; ks++) {
#pragma unroll
            for (int nt = 0; nt < 8; nt++) {
                uint32_t bh[2];
                bh[0] = __float_as_uint(Ks[(nt * 8 + lr) * KS_STRIDE + ks * 8 + lc]);
                bh[1] = __float_as_uint(Ks[(nt * 8 + lr) * KS_STRIDE + ks * 8 + lc + 4]);
                mma_tf32(sc[nt], &qh[ks * 4], bh);
                mma_tf32(sc[nt], &ql[ks * 4], bh);
            }
        }

        // Diagonal-block causal mask
        if (kv == qb) {
#pragma unroll
            for (int nt = 0; nt < 8; nt++)
#pragma unroll
                for (int j = 0; j < 4; j++) {
                    int col = nt * 8 + lc * 2 + (j & 1);
                    int row = warp * 16 + lr + (j >> 1) * 8;
                    if (col > row) sc[nt][j] = -INFINITY;
                }
        }

        // ---- online softmax ----
        float mnew[2] = {-INFINITY, -INFINITY};
#pragma unroll
        for (int nt = 0; nt < 8; nt++)
#pragma unroll
            for (int j = 0; j < 4; j++) mnew[j >> 1] = fmaxf(mnew[j >> 1], sc[nt][j]);
#pragma unroll
        for (int off = 1; off < 4; off <<= 1) {
            mnew[0] = fmaxf(mnew[0], __shfl_xor_sync(0xffffffffu, mnew[0], off));
            mnew[1] = fmaxf(mnew[1], __shfl_xor_sync(0xffffffffu, mnew[1], off));
        }
        float mtot0 = fmaxf(mrow[0], mnew[0]);
        float mtot1 = fmaxf(mrow[1], mnew[1]);
        float alpha0 = __expf(mrow[0] - mtot0);
        float alpha1 = __expf(mrow[1] - mtot1);
        mrow[0] = mtot0; mrow[1] = mtot1;

        float rs[2] = {0.f, 0.f};
#pragma unroll
        for (int nt = 0; nt < 8; nt++)
#pragma unroll
            for (int j = 0; j < 4; j++) {
                float p = __expf(sc[nt][j] - ((j >> 1) ? mtot1 : mtot0));
                sc[nt][j] = p;
                rs[j >> 1] += p;
            }
#pragma unroll
        for (int off = 1; off < 4; off <<= 1) {
            rs[0] += __shfl_xor_sync(0xffffffffu, rs[0], off);
            rs[1] += __shfl_xor_sync(0xffffffffu, rs[1], off);
        }
        lrow[0] = lrow[0] * alpha0 + rs[0];
        lrow[1] = lrow[1] * alpha1 + rs[1];

#pragma unroll
        for (int nt = 0; nt < 16; nt++) {
            acc[nt][0] *= alpha0; acc[nt][1] *= alpha0;
            acc[nt][2] *= alpha1; acc[nt][3] *= alpha1;
        }

        // P -> smem (per-warp private), rna-rounded
        float* Pw = Ps + warp * 16 * PS_STRIDE;
#pragma unroll
        for (int nt = 0; nt < 8; nt++)
#pragma unroll
            for (int j = 0; j < 4; j++) {
                int row = lr + (j >> 1) * 8;
                int col = nt * 8 + lc * 2 + (j & 1);
                Pw[row * PS_STRIDE + col] = __uint_as_float(to_tf32(sc[nt][j]));
            }
        __syncwarp();

        // ---- O += P @ V (1xTF32, V truncated by HW) ----
#pragma unroll
        for (int ks2 = 0; ks2 < 8; ks2++) {
            uint32_t pa[4];
            pa[0] = __float_as_uint(Pw[lr * PS_STRIDE + ks2 * 8 + lc]);
            pa[1] = __float_as_uint(Pw[(lr + 8) * PS_STRIDE + ks2 * 8 + lc]);
            pa[2] = __float_as_uint(Pw[lr * PS_STRIDE + ks2 * 8 + lc + 4]);
            pa[3] = __float_as_uint(Pw[(lr + 8) * PS_STRIDE + ks2 * 8 + lc + 4]);
#pragma unroll
            for (int nt2 = 0; nt2 < 16; nt2++) {
                uint32_t vb[2];
                vb[0] = __float_as_uint(Vs[(ks2 * 8 + lc) * VS_STRIDE + nt2 * 8 + lr]);
                vb[1] = __float_as_uint(Vs[(ks2 * 8 + lc + 4) * VS_STRIDE + nt2 * 8 + lr]);
                mma_tf32(acc[nt2], pa, vb);
            }
        }
    }

    // Epilogue
    float inv0 = 1.f / lrow[0];
    float inv1 = 1.f / lrow[1];
    size_t obase = ((size_t)b * S_LEN + qrow0) * H_DIM;
#pragma unroll
    for (int nt2 = 0; nt2 < 16; nt2++) {
        int col = nt2 * 8 + lc * 2;
        *(float2*)(out + obase + col) =
            make_float2(acc[nt2][0] * inv0, acc[nt2][1] * inv0);
        *(float2*)(out + obase + (size_t)8 * H_DIM + col) =
            make_float2(acc[nt2][2] * inv1, acc[nt2][3] * inv1);
    }
}

// ---------------- launch ----------------

extern "C" void kernel_launch(void* const* d_in, const int* in_sizes, int n_in,
                              void* d_out, int out_size) {
    const float* x     = (const float*)d_in[0];
    const float* w_dkv = (const float*)d_in[1];
    const float* w_k   = (const float*)d_in[2];
    const float* w_v   = (const float*)d_in[3];
    const float* w_q   = (const float*)d_in[4];

    float* out = (float*)d_out;                          // [B,S,HEAD]
    float* latent = out + (size_t)M_TOTAL * H_DIM;       // [B,S,LATENT]

    float *qp, *kp, *vp;
    cudaGetSymbolAddress((void**)&qp, g_q);
    cudaGetSymbolAddress((void**)&kp, g_k);
    cudaGetSymbolAddress((void**)&vp, g_v);

    constexpr int SMEM1 = 2 * (128 * 36 + 32 * (192 + 8)) * 4;  // 88064
    constexpr int SMEM2 = 2 * (128 * 36 + 32 * (64 + 8)) * 4;   // 55296

    static bool attrs_set = false;
    if (!attrs_set) {
        cudaFuncSetAttribute(gemm_kernel<192>,
                             cudaFuncAttributeMaxDynamicSharedMemorySize, SMEM1);
        cudaFuncSetAttribute(gemm_kernel<64>,
                             cudaFuncAttributeMaxDynamicSharedMemorySize, SMEM2);
        cudaFuncSetAttribute(attn_kernel,
                             cudaFuncAttributeMaxDynamicSharedMemorySize, ATTN_SMEM_BYTES);
        attrs_set = true;
    }

    // 1) latent = x@w_dkv (3x, cols<64) -> d_out latent; q = x@w_q (2x) -> scratch.
    gemm_kernel<192><<<dim3(M_TOTAL / 128, 1), 512, SMEM1>>>(
        x, w_dkv, w_q, latent, qp, E_DIM, L_DIM, H_DIM, 64);

    // 2) k = latent@w_k, v = latent@w_v (3x everywhere; K=64, cheap)
    gemm_kernel<64><<<dim3(M_TOTAL / 128, 4), 512, SMEM2>>>(
        latent, w_k, w_v, kp, vp, L_DIM, H_DIM, H_DIM, 1 << 30);

    // 3) causal flash attention
    attn_kernel<<<512, 128, ATTN_SMEM_BYTES>>>(qp, kp, vp, out);
}

// round 5
// speedup vs baseline: 1.8462x; 1.2757x over previous
#include <cuda_runtime.h>
#include <cstdint>

#define M_TOTAL 32768
#define E_DIM 2048
#define L_DIM 64
#define H_DIM 128
#define S_LEN 4096

// Scratch (device globals: allocation-free rule)
__device__ float g_q[(size_t)M_TOTAL * H_DIM];
__device__ float g_k[(size_t)M_TOTAL * H_DIM];
__device__ float g_v[(size_t)M_TOTAL * H_DIM];

// Pre-rounded (tf32-rna) weights, same layouts as inputs:
// [w_dkv (2048x64) | w_q (2048x128) | w_k (64x128) | w_v (64x128)]
#define WR_DKV 0
#define WR_Q   (2048 * 64)
#define WR_K   (WR_Q + 2048 * 128)
#define WR_V   (WR_K + 64 * 128)
#define WR_TOT (WR_V + 64 * 128)
__device__ float g_wr[WR_TOT];

// ---------------- tf32 / async helpers ----------------

__device__ __forceinline__ void mma_tf32(float* d, const uint32_t* a, const uint32_t* b) {
    asm volatile(
        "mma.sync.aligned.m16n8k8.row.col.f32.tf32.tf32.f32 "
        "{%0,%1,%2,%3}, {%4,%5,%6,%7}, {%8,%9}, {%0,%1,%2,%3};\n"
        : "+f"(d[0]), "+f"(d[1]), "+f"(d[2]), "+f"(d[3])
        : "r"(a[0]), "r"(a[1]), "r"(a[2]), "r"(a[3]), "r"(b[0]), "r"(b[1]));
}

__device__ __forceinline__ uint32_t to_tf32(float x) {
    uint32_t h;
    asm("cvt.rna.tf32.f32 %0, %1;" : "=r"(h) : "f"(x));
    return h;
}

__device__ __forceinline__ void split_tf32(float x, uint32_t& hi, uint32_t& lo) {
    uint32_t h = to_tf32(x);
    hi = h;
    lo = __float_as_uint(x - __uint_as_float(h));
}

__device__ __forceinline__ void cp16(void* dst, const void* src) {
    uint32_t d = (uint32_t)__cvta_generic_to_shared(dst);
    asm volatile("cp.async.cg.shared.global [%0], [%1], 16;\n" :: "r"(d), "l"(src));
}
#define CP_COMMIT asm volatile("cp.async.commit_group;\n")
#define CP_WAIT0  asm volatile("cp.async.wait_group 0;\n")
#define CP_WAIT1  asm volatile("cp.async.wait_group 1;\n")

// ---------------- weight pre-rounding (once per call, ~5us) ----------------

__global__ void prep_w(const float* __restrict__ w_dkv, const float* __restrict__ w_q,
                       const float* __restrict__ w_k, const float* __restrict__ w_v) {
    int i = blockIdx.x * 256 + threadIdx.x;
    float v;
    if (i < WR_Q)       v = w_dkv[i];
    else if (i < WR_K)  v = w_q[i - WR_Q];
    else if (i < WR_V)  v = w_k[i - WR_K];
    else                v = w_v[i - WR_V];
    g_wr[i] = __uint_as_float(to_tf32(v));
}

// ---------------- pipelined 2xTF32 GEMM ----------------
// C = A[M,K] @ concat(B1[K,N1], B2[K,N2]); B pre-rounded to tf32 (no cvt in loop).
// A split hi/lo (exact). BM=64, KT=32, 256 threads = 8 warps as 2(m) x 4(n).
// cp.async double-buffered. round_c: rna-round outputs on store.

template <int BN>
__global__ void __launch_bounds__(256, 2) gemm_kernel(
    const float* __restrict__ A,
    const float* __restrict__ B1, const float* __restrict__ B2,
    float* __restrict__ C1, float* __restrict__ C2,
    int K, int N1, int N2, int round_c)
{
    constexpr int BM = 64;
    constexpr int KTL = 32;
    constexpr int WNT = BN / 32;            // n8 tiles per warp (4 n-warps)
    constexpr int ASTR = KTL + 4;           // 36
    constexpr int BSTR = BN + 8;
    constexpr int ASZ = BM * ASTR;
    constexpr int BSZ = KTL * BSTR;
    constexpr int BUF = ASZ + BSZ;

    extern __shared__ float sh[];

    const int tid = threadIdx.x;
    const int warp = tid >> 5, lane = tid & 31;
    const int wm = warp >> 2;               // 0..1 -> 32 rows each
    const int wn = warp & 3;                // 0..3 -> BN/4 cols each
    const int lr = lane >> 2, lc = lane & 3;
    const int m0 = blockIdx.x * BM;
    const int n0 = blockIdx.y * BN;

    const int arow = tid >> 2;              // 0..63
    const int ac4 = (tid & 3) * 4;          // 0,4,8,12 (+16 for second)

    float acc[2][WNT][4];
#pragma unroll
    for (int mt = 0; mt < 2; mt++)
#pragma unroll
        for (int nt = 0; nt < WNT; nt++)
#pragma unroll
            for (int j = 0; j < 4; j++) acc[mt][nt][j] = 0.f;

    const int nk = K / KTL;

    // prologue: stage tile 0
    {
        float* As = sh;
        float* Bs = sh + ASZ;
        cp16(&As[arow * ASTR + ac4],      A + (size_t)(m0 + arow) * K + ac4);
        cp16(&As[arow * ASTR + ac4 + 16], A + (size_t)(m0 + arow) * K + ac4 + 16);
        constexpr int NB = (KTL * BN / 4) / 256;
#pragma unroll
        for (int it = 0; it < NB; it++) {
            int i = it * 256 + tid;
            int brow = i / (BN / 4);
            int bc4 = (i % (BN / 4)) * 4;
            int gc = n0 + bc4;
            const float* src = (gc < N1) ? (B1 + (size_t)brow * N1 + gc)
                                         : (B2 + (size_t)brow * N2 + (gc - N1));
            cp16(&Bs[brow * BSTR + bc4], src);
        }
        CP_COMMIT;
    }

    for (int kt = 0; kt < nk; kt++) {
        if (kt + 1 < nk) {
            float* As = sh + ((kt + 1) & 1) * BUF;
            float* Bs = As + ASZ;
            int kb = (kt + 1) * KTL;
            cp16(&As[arow * ASTR + ac4],      A + (size_t)(m0 + arow) * K + kb + ac4);
            cp16(&As[arow * ASTR + ac4 + 16], A + (size_t)(m0 + arow) * K + kb + ac4 + 16);
            constexpr int NB = (KTL * BN / 4) / 256;
#pragma unroll
            for (int it = 0; it < NB; it++) {
                int i = it * 512;  // placeholder, fixed below
                i = it * 256 + tid;
                int brow = i / (BN / 4);
                int bc4 = (i % (BN / 4)) * 4;
                int gc = n0 + bc4;
                const float* src = (gc < N1) ? (B1 + (size_t)(kb + brow) * N1 + gc)
                                             : (B2 + (size_t)(kb + brow) * N2 + (gc - N1));
                cp16(&Bs[brow * BSTR + bc4], src);
            }
            CP_COMMIT;
            CP_WAIT1;
        } else {
            CP_WAIT0;
        }
        __syncthreads();

        const float* As = sh + (kt & 1) * BUF;
        const float* Bs = As + ASZ;

#pragma unroll
        for (int ks = 0; ks < 4; ks++) {
            uint32_t ah[2][4], al[2][4];
#pragma unroll
            for (int mt = 0; mt < 2; mt++) {
                int rb = wm * 32 + mt * 16;
                split_tf32(As[(rb + lr) * ASTR + ks * 8 + lc],         ah[mt][0], al[mt][0]);
                split_tf32(As[(rb + lr + 8) * ASTR + ks * 8 + lc],     ah[mt][1], al[mt][1]);
                split_tf32(As[(rb + lr) * ASTR + ks * 8 + lc + 4],     ah[mt][2], al[mt][2]);
                split_tf32(As[(rb + lr + 8) * ASTR + ks * 8 + lc + 4], ah[mt][3], al[mt][3]);
            }
#pragma unroll
            for (int nt = 0; nt < WNT; nt++) {
                int c0 = wn * (BN / 4) + nt * 8 + lr;
                uint32_t bh[2];
                bh[0] = __float_as_uint(Bs[(ks * 8 + lc) * BSTR + c0]);
                bh[1] = __float_as_uint(Bs[(ks * 8 + lc + 4) * BSTR + c0]);
#pragma unroll
                for (int mt = 0; mt < 2; mt++) {
                    mma_tf32(acc[mt][nt], ah[mt], bh);
                    mma_tf32(acc[mt][nt], al[mt], bh);
                }
            }
        }
        __syncthreads();
    }

    // Store (optionally rna-rounded: used for k/v so attention's HW truncation is exact)
#pragma unroll
    for (int mt = 0; mt < 2; mt++) {
        int r0 = m0 + wm * 32 + mt * 16 + lr;
#pragma unroll
        for (int nt = 0; nt < WNT; nt++) {
            int gc = n0 + wn * (BN / 4) + nt * 8 + lc * 2;
            float* dst;
            int stride, col;
            if (gc < N1) { dst = C1; stride = N1; col = gc; }
            else         { dst = C2; stride = N2; col = gc - N1; }
            float o0 = acc[mt][nt][0], o1 = acc[mt][nt][1];
            float o2 = acc[mt][nt][2], o3 = acc[mt][nt][3];
            if (round_c) {
                o0 = __uint_as_float(to_tf32(o0));
                o1 = __uint_as_float(to_tf32(o1));
                o2 = __uint_as_float(to_tf32(o2));
                o3 = __uint_as_float(to_tf32(o3));
            }
            *(float2*)(dst + (size_t)r0 * stride + col)       = make_float2(o0, o1);
            *(float2*)(dst + (size_t)(r0 + 8) * stride + col) = make_float2(o2, o3);
        }
    }
}

// ---------------- Flash attention (causal) ----------------
// BLOCK_M=64 (4 warps x 16 rows), BLOCK_N=64, HEAD=128.
// QK^T: 2xTF32 (q pre-split hi/lo in regs; K already tf32-rna from gemm2).
// PV: 1xTF32 (P rna; V already tf32-rna from gemm2).

constexpr int KS_STRIDE = 132;
constexpr int VS_STRIDE = 136;
constexpr int PS_STRIDE = 68;
constexpr int ATTN_SMEM_BYTES = (64 * KS_STRIDE + 64 * VS_STRIDE + 64 * PS_STRIDE) * 4;

__global__ void __launch_bounds__(128, 2) attn_kernel(
    const float* __restrict__ q, const float* __restrict__ k,
    const float* __restrict__ v, float* __restrict__ out)
{
    extern __shared__ float sm[];
    float* Ks = sm;
    float* Vs = sm + 64 * KS_STRIDE;
    float* Ps = Vs + 64 * VS_STRIDE;

    const int idx = blockIdx.x;
    const int b = idx & 7;
    const int qb = 63 - (idx >> 3);         // longest first
    const int tid = threadIdx.x;
    const int warp = tid >> 5, lane = tid & 31;
    const int lr = lane >> 2, lc = lane & 3;

    const float* qB = q + (size_t)b * S_LEN * H_DIM;
    const float* kB = k + (size_t)b * S_LEN * H_DIM;
    const float* vB = v + (size_t)b * S_LEN * H_DIM;

    const int qrow0 = qb * 64 + warp * 16 + lr;
    const float SCALE = 0.08838834764831845f;  // 1/sqrt(128)

    // q fragments pre-split hi/lo, kept in registers for all 16 k-steps
    uint32_t qh[64], ql[64];
#pragma unroll
    for (int ks = 0; ks < 16; ks++) {
        int c = ks * 8 + lc;
        split_tf32(qB[(size_t)qrow0 * H_DIM + c] * SCALE,       qh[ks * 4 + 0], ql[ks * 4 + 0]);
        split_tf32(qB[(size_t)(qrow0 + 8) * H_DIM + c] * SCALE, qh[ks * 4 + 1], ql[ks * 4 + 1]);
        split_tf32(qB[(size_t)qrow0 * H_DIM + c + 4] * SCALE,       qh[ks * 4 + 2], ql[ks * 4 + 2]);
        split_tf32(qB[(size_t)(qrow0 + 8) * H_DIM + c + 4] * SCALE, qh[ks * 4 + 3], ql[ks * 4 + 3]);
    }

    float acc[16][4];
#pragma unroll
    for (int nt = 0; nt < 16; nt++)
#pragma unroll
        for (int j = 0; j < 4; j++) acc[nt][j] = 0.f;
    float mrow[2] = {-INFINITY, -INFINITY};
    float lrow[2] = {0.f, 0.f};

    const int row64 = tid >> 5;
    const int c4 = (tid & 31) * 4;

    for (int kv = 0; kv <= qb; kv++) {
        __syncthreads();  // previous tile's readers done before overwrite

        // cp.async K,V tiles (64x128 each); values already tf32-rounded by gemm2
#pragma unroll
        for (int rnd = 0; rnd < 16; rnd++) {
            int row = row64 + rnd * 4;
            cp16(&Ks[row * KS_STRIDE + c4], kB + (size_t)(kv * 64 + row) * H_DIM + c4);
            cp16(&Vs[row * VS_STRIDE + c4], vB + (size_t)(kv * 64 + row) * H_DIM + c4);
        }
        CP_COMMIT;
        CP_WAIT0;
        __syncthreads();

        // ---- S = q @ k^T (2xTF32) ----
        float sc[8][4];
#pragma unroll
        for (int nt = 0; nt < 8; nt++)
#pragma unroll
            for (int j = 0; j < 4; j++) sc[nt][j] = 0.f;

#pragma unroll
        for (int ks = 0; ks < 16; ks++) {
#pragma unroll
            for (int nt = 0; nt < 8; nt++) {
                uint32_t bh[2];
                bh[0] = __float_as_uint(Ks[(nt * 8 + lr) * KS_STRIDE + ks * 8 + lc]);
                bh[1] = __float_as_uint(Ks[(nt * 8 + lr) * KS_STRIDE + ks * 8 + lc + 4]);
                mma_tf32(sc[nt], &qh[ks * 4], bh);
                mma_tf32(sc[nt], &ql[ks * 4], bh);
            }
        }

        // Diagonal-block causal mask
        if (kv == qb) {
#pragma unroll
            for (int nt = 0; nt < 8; nt++)
#pragma unroll
                for (int j = 0; j < 4; j++) {
                    int col = nt * 8 + lc * 2 + (j & 1);
                    int row = warp * 16 + lr + (j >> 1) * 8;
                    if (col > row) sc[nt][j] = -INFINITY;
                }
        }

        // ---- online softmax ----
        float mnew[2] = {-INFINITY, -INFINITY};
#pragma unroll
        for (int nt = 0; nt < 8; nt++)
#pragma unroll
            for (int j = 0; j < 4; j++) mnew[j >> 1] = fmaxf(mnew[j >> 1], sc[nt][j]);
#pragma unroll
        for (int off = 1; off < 4; off <<= 1) {
            mnew[0] = fmaxf(mnew[0], __shfl_xor_sync(0xffffffffu, mnew[0], off));
            mnew[1] = fmaxf(mnew[1], __shfl_xor_sync(0xffffffffu, mnew[1], off));
        }
        float mtot0 = fmaxf(mrow[0], mnew[0]);
        float mtot1 = fmaxf(mrow[1], mnew[1]);
        float alpha0 = __expf(mrow[0] - mtot0);
        float alpha1 = __expf(mrow[1] - mtot1);
        mrow[0] = mtot0; mrow[1] = mtot1;

        float rs[2] = {0.f, 0.f};
#pragma unroll
        for (int nt = 0; nt < 8; nt++)
#pragma unroll
            for (int j = 0; j < 4; j++) {
                float p = __expf(sc[nt][j] - ((j >> 1) ? mtot1 : mtot0));
                sc[nt][j] = p;
                rs[j >> 1] += p;
            }
#pragma unroll
        for (int off = 1; off < 4; off <<= 1) {
            rs[0] += __shfl_xor_sync(0xffffffffu, rs[0], off);
            rs[1] += __shfl_xor_sync(0xffffffffu, rs[1], off);
        }
        lrow[0] = lrow[0] * alpha0 + rs[0];
        lrow[1] = lrow[1] * alpha1 + rs[1];

#pragma unroll
        for (int nt = 0; nt < 16; nt++) {
            acc[nt][0] *= alpha0; acc[nt][1] *= alpha0;
            acc[nt][2] *= alpha1; acc[nt][3] *= alpha1;
        }

        // P -> smem (per-warp private), rna-rounded
        float* Pw = Ps + warp * 16 * PS_STRIDE;
#pragma unroll
        for (int nt = 0; nt < 8; nt++)
#pragma unroll
            for (int j = 0; j < 4; j++) {
                int row = lr + (j >> 1) * 8;
                int col = nt * 8 + lc * 2 + (j & 1);
                Pw[row * PS_STRIDE + col] = __uint_as_float(to_tf32(sc[nt][j]));
            }
        __syncwarp();

        // ---- O += P @ V (1xTF32) ----
#pragma unroll
        for (int ks2 = 0; ks2 < 8; ks2++) {
            uint32_t pa[4];
            pa[0] = __float_as_uint(Pw[lr * PS_STRIDE + ks2 * 8 + lc]);
            pa[1] = __float_as_uint(Pw[(lr + 8) * PS_STRIDE + ks2 * 8 + lc]);
            pa[2] = __float_as_uint(Pw[lr * PS_STRIDE + ks2 * 8 + lc + 4]);
            pa[3] = __float_as_uint(Pw[(lr + 8) * PS_STRIDE + ks2 * 8 + lc + 4]);
#pragma unroll
            for (int nt2 = 0; nt2 < 16; nt2++) {
                uint32_t vb[2];
                vb[0] = __float_as_uint(Vs[(ks2 * 8 + lc) * VS_STRIDE + nt2 * 8 + lr]);
                vb[1] = __float_as_uint(Vs[(ks2 * 8 + lc + 4) * VS_STRIDE + nt2 * 8 + lr]);
                mma_tf32(acc[nt2], pa, vb);
            }
        }
    }

    // Epilogue
    float inv0 = 1.f / lrow[0];
    float inv1 = 1.f / lrow[1];
    size_t obase = ((size_t)b * S_LEN + qrow0) * H_DIM;
#pragma unroll
    for (int nt2 = 0; nt2 < 16; nt2++) {
        int col = nt2 * 8 + lc * 2;
        *(float2*)(out + obase + col) =
            make_float2(acc[nt2][0] * inv0, acc[nt2][1] * inv0);
        *(float2*)(out + obase + (size_t)8 * H_DIM + col) =
            make_float2(acc[nt2][2] * inv1, acc[nt2][3] * inv1);
    }
}

// ---------------- launch ----------------

extern "C" void kernel_launch(void* const* d_in, const int* in_sizes, int n_in,
                              void* d_out, int out_size) {
    const float* x     = (const float*)d_in[0];
    const float* w_dkv = (const float*)d_in[1];
    const float* w_k   = (const float*)d_in[2];
    const float* w_v   = (const float*)d_in[3];
    const float* w_q   = (const float*)d_in[4];

    float* out = (float*)d_out;                          // [B,S,HEAD]
    float* latent = out + (size_t)M_TOTAL * H_DIM;       // [B,S,LATENT]

    float *qp, *kp, *vp, *wr;
    cudaGetSymbolAddress((void**)&qp, g_q);
    cudaGetSymbolAddress((void**)&kp, g_k);
    cudaGetSymbolAddress((void**)&vp, g_v);
    cudaGetSymbolAddress((void**)&wr, g_wr);

    constexpr int SMEM1 = 2 * (64 * 36 + 32 * (192 + 8)) * 4;  // 69632
    constexpr int SMEM2 = 2 * (64 * 36 + 32 * (64 + 8)) * 4;   // 36864

    static bool attrs_set = false;
    if (!attrs_set) {
        cudaFuncSetAttribute(gemm_kernel<192>,
                             cudaFuncAttributeMaxDynamicSharedMemorySize, SMEM1);
        cudaFuncSetAttribute(gemm_kernel<64>,
                             cudaFuncAttributeMaxDynamicSharedMemorySize, SMEM2);
        cudaFuncSetAttribute(attn_kernel,
                             cudaFuncAttributeMaxDynamicSharedMemorySize, ATTN_SMEM_BYTES);
        attrs_set = true;
    }

    // 0) pre-round all weights to tf32-rna (unbiased)
    prep_w<<<WR_TOT / 256, 256>>>(w_dkv, w_q, w_k, w_v);

    // 1) latent = x@w_dkv -> d_out latent region; q = x@w_q -> scratch (fp32 out)
    gemm_kernel<192><<<dim3(M_TOTAL / 64, 1), 256, SMEM1>>>(
        x, wr + WR_DKV, wr + WR_Q, latent, qp, E_DIM, L_DIM, H_DIM, 0);

    // 2) k = latent@w_k, v = latent@w_v -> scratch, rna-rounded on store
    gemm_kernel<64><<<dim3(M_TOTAL / 64, 4), 256, SMEM2>>>(
        latent, wr + WR_K, wr + WR_V, kp, vp, L_DIM, H_DIM, H_DIM, 1);

    // 3) causal flash attention
    attn_kernel<<<512, 128, ATTN_SMEM_BYTES>>>(qp, kp, vp, out);
}